// round 2
// baseline (speedup 1.0000x reference)
#include <cuda_runtime.h>

// ---------------------------------------------------------------------------
// Attention_49048526520431 : out[b,d] = sum_q softmax(q k^T / sqrt(D))[q,:] @ v
//                                     = sum_k (sum_q attn[q,k]) * v[k,d]
// B=16, S=2048, D=256, fp32.
// Stages:
//   1) q,k,v = x@W + b            (3x GEMM  M=32768,N=256,K=256)
//   2) energy = q k^T / 16        (batched GEMM M=N=2048,K=256, 16 batches)
//   3) per-row (max, 1/sumexp)
//   4) w[b,k] = sum_q exp(e-mx)*inv_sum   (column sums)
//   5) out[b,d] = sum_k w[b,k] v[b,k,d]
// ---------------------------------------------------------------------------

#define BM 128
#define BN 128
#define BK 8
#define TM 8
#define TN 8

static const int Bb = 16;
static const int Ss = 2048;
static const int Dd = 256;

__device__ float g_q[16 * 2048 * 256];
__device__ float g_k[16 * 2048 * 256];
__device__ float g_v[16 * 2048 * 256];
__device__ float g_energy[67108864];   // 16 * 2048 * 2048
__device__ float g_mx[16 * 2048];
__device__ float g_is[16 * 2048];
__device__ float g_w[16 * 2048];

// ---------------------------------------------------------------------------
// Register-blocked fp32 GEMM: C = scale * A * op(B) (+ bias)
//   TRANSB=false: B is [K,N] row-major   (projections)
//   TRANSB=true : B is [N,K] row-major   (energy: q k^T)
// 128x128 tile, BK=8, 256 threads, 8x8 microtile per thread.
// blockIdx.z selects batch via strides sA/sB/sC.
// ---------------------------------------------------------------------------
template <bool TRANSB, bool HASBIAS>
__global__ __launch_bounds__(256, 2)
void gemm_kernel(const float* __restrict__ A, const float* __restrict__ B,
                 const float* __restrict__ bias, float* __restrict__ C,
                 int M, int N, int K,
                 long long sA, long long sB, long long sC, float scale) {
    __shared__ float As[BK][BM];
    __shared__ float Bs[BK][BN];

    A += (long long)blockIdx.z * sA;
    B += (long long)blockIdx.z * sB;
    C += (long long)blockIdx.z * sC;

    const int bm = blockIdx.y * BM;
    const int bn = blockIdx.x * BN;
    const int t  = threadIdx.x;
    const int tx = t & 15;        // 0..15
    const int ty = t >> 4;        // 0..15

    float acc[TM][TN];
#pragma unroll
    for (int i = 0; i < TM; i++)
#pragma unroll
        for (int j = 0; j < TN; j++) acc[i][j] = 0.0f;

    // A tile loader: each thread loads one float4 along K.
    const int arow = t >> 1;            // 0..127
    const int acol = (t & 1) * 4;       // 0 or 4
    const float* Aptr = A + (long long)(bm + arow) * K + acol;

    // B tile loader
    const float* Bptr;
    int brow, bcol;
    if (TRANSB) {
        brow = t >> 1;                  // n index 0..127
        bcol = (t & 1) * 4;             // k offset
        Bptr = B + (long long)(bn + brow) * K + bcol;
    } else {
        brow = t >> 5;                  // k index 0..7
        bcol = (t & 31) * 4;            // n offset 0..124
        Bptr = B + (long long)brow * N + bn + bcol;
    }

    for (int k0 = 0; k0 < K; k0 += BK) {
        float4 av = *(const float4*)(Aptr + k0);
        As[acol + 0][arow] = av.x;
        As[acol + 1][arow] = av.y;
        As[acol + 2][arow] = av.z;
        As[acol + 3][arow] = av.w;

        if (TRANSB) {
            float4 bv = *(const float4*)(Bptr + k0);
            Bs[bcol + 0][brow] = bv.x;
            Bs[bcol + 1][brow] = bv.y;
            Bs[bcol + 2][brow] = bv.z;
            Bs[bcol + 3][brow] = bv.w;
        } else {
            float4 bv = *(const float4*)(Bptr + (long long)k0 * N);
            *(float4*)&Bs[brow][bcol] = bv;
        }
        __syncthreads();

#pragma unroll
        for (int kk = 0; kk < BK; kk++) {
            float4 a0 = *(const float4*)&As[kk][ty * TM];
            float4 a1 = *(const float4*)&As[kk][ty * TM + 4];
            float4 b0 = *(const float4*)&Bs[kk][tx * TN];
            float4 b1 = *(const float4*)&Bs[kk][tx * TN + 4];
            float ar[8] = {a0.x, a0.y, a0.z, a0.w, a1.x, a1.y, a1.z, a1.w};
            float br[8] = {b0.x, b0.y, b0.z, b0.w, b1.x, b1.y, b1.z, b1.w};
#pragma unroll
            for (int i = 0; i < TM; i++)
#pragma unroll
                for (int j = 0; j < TN; j++)
                    acc[i][j] = fmaf(ar[i], br[j], acc[i][j]);
        }
        __syncthreads();
    }

#pragma unroll
    for (int i = 0; i < TM; i++) {
        const int row = bm + ty * TM + i;
#pragma unroll
        for (int j = 0; j < TN; j++) {
            const int col = bn + tx * TN + j;
            float v = acc[i][j] * scale;
            if (HASBIAS) v += bias[col];
            C[(long long)row * N + col] = v;
        }
    }
}

// ---------------------------------------------------------------------------
// Per-row softmax stats: max and 1/sum(exp(e-max)). One block per (b,q) row.
// ---------------------------------------------------------------------------
__global__ void row_stats_kernel() {
    const int r = blockIdx.x;                        // 0..32767
    const float* e = g_energy + (long long)r * 2048;
    const int t = threadIdx.x;                       // 256 threads
    __shared__ float red[256];

    float m = -3.4e38f;
    for (int i = t; i < 2048; i += 256) m = fmaxf(m, e[i]);
    red[t] = m;
    __syncthreads();
    for (int s = 128; s > 0; s >>= 1) {
        if (t < s) red[t] = fmaxf(red[t], red[t + s]);
        __syncthreads();
    }
    const float mx = red[0];
    __syncthreads();

    float sm = 0.0f;
    for (int i = t; i < 2048; i += 256) sm += __expf(e[i] - mx);
    red[t] = sm;
    __syncthreads();
    for (int s = 128; s > 0; s >>= 1) {
        if (t < s) red[t] += red[t + s];
        __syncthreads();
    }
    if (t == 0) {
        g_mx[r] = mx;
        g_is[r] = 1.0f / red[0];
    }
}

// ---------------------------------------------------------------------------
// Column sums of the normalized attention matrix: w[b,k] = sum_q p[q,k].
// Grid (16, 8), 256 threads; thread owns one k column in its 256-chunk.
// ---------------------------------------------------------------------------
__global__ void colsum_kernel() {
    const int b = blockIdx.x;
    const int k = blockIdx.y * 256 + threadIdx.x;
    const float* e  = g_energy + (long long)b * 2048 * 2048 + k;
    const float* mx = g_mx + b * 2048;
    const float* is = g_is + b * 2048;
    float acc = 0.0f;
#pragma unroll 8
    for (int q = 0; q < 2048; q++)
        acc += __expf(e[(long long)q * 2048] - mx[q]) * is[q];
    g_w[b * 2048 + k] = acc;
}

// ---------------------------------------------------------------------------
// Final contraction: out[b,d] = sum_k w[b,k] * v[b,k,d]
// ---------------------------------------------------------------------------
__global__ void out_kernel(float* __restrict__ out) {
    const int b = blockIdx.x;
    const int d = threadIdx.x;                       // 256 threads
    const float* w = g_w + b * 2048;
    const float* v = g_v + (long long)b * 2048 * 256 + d;
    float acc = 0.0f;
#pragma unroll 8
    for (int kk = 0; kk < 2048; kk++)
        acc = fmaf(w[kk], v[(long long)kk * 256], acc);
    out[b * 256 + d] = acc;
}

// ---------------------------------------------------------------------------
extern "C" void kernel_launch(void* const* d_in, const int* in_sizes, int n_in,
                              void* d_out, int out_size) {
    (void)in_sizes; (void)n_in; (void)out_size;
    const float* x  = (const float*)d_in[0];
    const float* Wq = (const float*)d_in[1];
    const float* bq = (const float*)d_in[2];
    const float* Wk = (const float*)d_in[3];
    const float* bk = (const float*)d_in[4];
    const float* Wv = (const float*)d_in[5];
    const float* bv = (const float*)d_in[6];
    float* out = (float*)d_out;

    float *pq, *pk, *pv, *pe;
    cudaGetSymbolAddress((void**)&pq, g_q);
    cudaGetSymbolAddress((void**)&pk, g_k);
    cudaGetSymbolAddress((void**)&pv, g_v);
    cudaGetSymbolAddress((void**)&pe, g_energy);

    const int MS = Bb * Ss;                   // 32768
    // 1) projections: M=32768, N=256, K=256 -> grid (N/BN=2, M/BM=256)
    dim3 gproj(Dd / BN, MS / BM, 1);
    gemm_kernel<false, true><<<gproj, 256>>>(x, Wq, bq, pq, MS, Dd, Dd, 0, 0, 0, 1.0f);
    gemm_kernel<false, true><<<gproj, 256>>>(x, Wk, bk, pk, MS, Dd, Dd, 0, 0, 0, 1.0f);
    gemm_kernel<false, true><<<gproj, 256>>>(x, Wv, bv, pv, MS, Dd, Dd, 0, 0, 0, 1.0f);

    // 2) energy = q k^T / 16 : batched, M=N=2048, K=256
    dim3 gen(Ss / BN, Ss / BM, Bb);
    gemm_kernel<true, false><<<gen, 256>>>(pq, pk, nullptr, pe, Ss, Ss, Dd,
                                           (long long)Ss * Dd, (long long)Ss * Dd,
                                           (long long)Ss * Ss, 0.0625f);

    // 3) row stats
    row_stats_kernel<<<MS, 256>>>();

    // 4) column sums
    colsum_kernel<<<dim3(Bb, Ss / 256), 256>>>();

    // 5) final contraction
    out_kernel<<<Bb, 256>>>(out);
}

// round 4
// speedup vs baseline: 1.3422x; 1.3422x over previous
#include <cuda_runtime.h>
#include <cuda_bf16.h>
#include <cstdint>

// ---------------------------------------------------------------------------
// Attention_49048526520431 on GB300 (sm_103a via compute_103 family target).
//   out[b,d] = sum_k (sum_q softmax(q k^T /16)[q,k]) * v[b,k,d]
// B=16, S=2048, D=256 fp32.
//
// tcgen05 is rejected by this bench's PTX target (compute_103, no "a"), so all
// GEMMs use family-portable mma.sync.m16n8k16 bf16 (HMMA) + ldmatrix + cp.async.
//
// Split-precision: fp32 a ~= a_hi + a_lo (both bf16).
//   A' = [a_hi | a_hi | a_lo]  (K'=768),  B' = [b_hi | b_lo | b_hi]
//   sum A'B' = hi*hi + hi*lo + lo*hi  (error ~2^-17, fp32 accumulate)
// ---------------------------------------------------------------------------

#define KTOT 768
#define NCHUNK 24            /* 768 / 32 */
#define KPAD 40              /* bf16 row stride in smem (80 bytes) */

__device__ __nv_bfloat16 g_xs[32768 * KTOT];     // x split, A-pattern
__device__ __nv_bfloat16 g_wtq[256 * KTOT];      // W^T split, B-pattern
__device__ __nv_bfloat16 g_wtk[256 * KTOT];
__device__ __nv_bfloat16 g_wtv[256 * KTOT];
__device__ __nv_bfloat16 g_qs[16 * 2048 * KTOT]; // q split, A-pattern
__device__ __nv_bfloat16 g_ks[16 * 2048 * KTOT]; // k split, B-pattern
__device__ float g_v[16 * 2048 * 256];
__device__ float g_energy[67108864];             // 16 * 2048 * 2048
__device__ float g_mx[16 * 2048];
__device__ float g_is[16 * 2048];
__device__ float g_w[16 * 2048];

// ----------------------------- PTX helpers ---------------------------------
__device__ __forceinline__ uint32_t smem_u32(const void* p) {
    uint32_t a;
    asm("{ .reg .u64 t; cvta.to.shared.u64 t, %1; cvt.u32.u64 %0, t; }" : "=r"(a) : "l"(p));
    return a;
}
__device__ __forceinline__ void cp16(uint32_t s, const void* g) {
    asm volatile("cp.async.cg.shared.global [%0], [%1], 16;" :: "r"(s), "l"(g));
}
#define CP_COMMIT() asm volatile("cp.async.commit_group;" ::: "memory")
#define CP_WAIT(n)  asm volatile("cp.async.wait_group %0;" :: "n"(n) : "memory")

__device__ __forceinline__ void ldmx4(uint32_t a, uint32_t& r0, uint32_t& r1,
                                      uint32_t& r2, uint32_t& r3) {
    asm volatile("ldmatrix.sync.aligned.m8n8.x4.shared.b16 {%0,%1,%2,%3}, [%4];"
                 : "=r"(r0), "=r"(r1), "=r"(r2), "=r"(r3) : "r"(a));
}
__device__ __forceinline__ void mma16816(float* c, uint32_t a0, uint32_t a1,
                                         uint32_t a2, uint32_t a3,
                                         uint32_t b0, uint32_t b1) {
    asm volatile(
        "mma.sync.aligned.m16n8k16.row.col.f32.bf16.bf16.f32 "
        "{%0,%1,%2,%3}, {%4,%5,%6,%7}, {%8,%9}, {%0,%1,%2,%3};"
        : "+f"(c[0]), "+f"(c[1]), "+f"(c[2]), "+f"(c[3])
        : "r"(a0), "r"(a1), "r"(a2), "r"(a3), "r"(b0), "r"(b1));
}

// ---------------------------------------------------------------------------
// Split prep kernels
// ---------------------------------------------------------------------------
__global__ void split_x_kernel(const float* __restrict__ x) {
    long long i = (long long)blockIdx.x * 256 + threadIdx.x;
    long long row = i >> 8;
    int col = (int)(i & 255);
    float v = x[i];
    __nv_bfloat16 hi = __float2bfloat16(v);
    __nv_bfloat16 lo = __float2bfloat16(v - __bfloat162float(hi));
    __nv_bfloat16* o = g_xs + row * KTOT;
    o[col] = hi; o[col + 256] = hi; o[col + 512] = lo;          // A-pattern
}

__global__ void split_w_kernel(const float* __restrict__ W, __nv_bfloat16* __restrict__ Wt) {
    int n = blockIdx.x;
    int k = threadIdx.x;
    float v = W[k * 256 + n];                                   // transpose
    __nv_bfloat16 hi = __float2bfloat16(v);
    __nv_bfloat16 lo = __float2bfloat16(v - __bfloat162float(hi));
    __nv_bfloat16* o = Wt + n * KTOT;
    o[k] = hi; o[k + 256] = lo; o[k + 512] = hi;                // B-pattern
}

// ---------------------------------------------------------------------------
// bf16 HMMA GEMM: D[m,n] = scale * sum_k A[m,k]*B[n,k] (+bias), K'=768.
// 128x128 CTA tile, 8 warps (4m x 2n), warp tile 32x64, BK=32, double-buffered
// cp.async. MODE 0: energy->g_energy (batched z). MODE 1: v (+bias).
// MODE 2: q split A-pattern. MODE 3: k split B-pattern.
// ---------------------------------------------------------------------------
template <int MODE>
__global__ __launch_bounds__(256, 2) void hmma_gemm(
    const __nv_bfloat16* __restrict__ A, const __nv_bfloat16* __restrict__ B,
    const float* __restrict__ bias, float* __restrict__ Cf,
    __nv_bfloat16* __restrict__ Cb, long long strideA, long long strideB,
    float scale)
{
    __shared__ __align__(128) __nv_bfloat16 sA[2][128 * KPAD];
    __shared__ __align__(128) __nv_bfloat16 sB[2][128 * KPAD];

    const int tid = threadIdx.x;
    const int lid = tid & 31;
    const int wid = tid >> 5;
    const int wm = (wid & 3) * 32;       // warp m offset in tile
    const int wn = (wid >> 2) * 64;      // warp n offset in tile
    const int n0 = blockIdx.x * 128;
    const int m0 = blockIdx.y * 128;
    A += (long long)blockIdx.z * strideA;
    B += (long long)blockIdx.z * strideB;

    // loader indices: 512 x 16B chunks per tile, 2 per thread
    const int lr0 = tid >> 2;            // row 0..63   (+64 on second iter)
    const int lc0 = (tid & 3) * 8;       // bf16 col: 0,8,16,24
    const float kscale = scale;

    float acc[2][8][4];
#pragma unroll
    for (int i = 0; i < 2; i++)
#pragma unroll
        for (int j = 0; j < 8; j++)
#pragma unroll
            for (int q = 0; q < 4; q++) acc[i][j][q] = 0.0f;

    uint32_t sAb[2], sBb[2];
    sAb[0] = smem_u32(&sA[0][0]); sAb[1] = smem_u32(&sA[1][0]);
    sBb[0] = smem_u32(&sB[0][0]); sBb[1] = smem_u32(&sB[1][0]);

    // ldmatrix lane addressing (row = lid%16, col8 = (lid/16)*8)
    const int xrow = lid & 15;
    const int xcol = (lid >> 4) * 8;

    auto load_chunk = [&](int c) {
        const int k0 = c * 32;
        const int b = c & 1;
#pragma unroll
        for (int i = 0; i < 2; i++) {
            int r = lr0 + i * 64;
            cp16(sAb[b] + (r * KPAD + lc0) * 2,
                 A + (long long)(m0 + r) * KTOT + k0 + lc0);
            cp16(sBb[b] + (r * KPAD + lc0) * 2,
                 B + (long long)(n0 + r) * KTOT + k0 + lc0);
        }
    };

    load_chunk(0);
    CP_COMMIT();

    for (int c = 0; c < NCHUNK; c++) {
        if (c + 1 < NCHUNK) { load_chunk(c + 1); CP_COMMIT(); CP_WAIT(1); }
        else CP_WAIT(0);
        __syncthreads();
        const int b = c & 1;
#pragma unroll
        for (int kf = 0; kf < 2; kf++) {
            uint32_t a[2][4];
#pragma unroll
            for (int mf = 0; mf < 2; mf++)
                ldmx4(sAb[b] + ((wm + mf * 16 + xrow) * KPAD + kf * 16 + xcol) * 2,
                      a[mf][0], a[mf][1], a[mf][2], a[mf][3]);
#pragma unroll
            for (int np = 0; np < 4; np++) {       // pairs of n-frags (16 cols)
                uint32_t r0, r1, r2, r3;
                ldmx4(sBb[b] + ((wn + np * 16 + xrow) * KPAD + kf * 16 + xcol) * 2,
                      r0, r1, r2, r3);
#pragma unroll
                for (int mf = 0; mf < 2; mf++) {
                    mma16816(acc[mf][np * 2 + 0], a[mf][0], a[mf][1], a[mf][2], a[mf][3], r0, r2);
                    mma16816(acc[mf][np * 2 + 1], a[mf][0], a[mf][1], a[mf][2], a[mf][3], r1, r3);
                }
            }
        }
        __syncthreads();
    }

    // ------------------------------ epilogue -------------------------------
#pragma unroll
    for (int mf = 0; mf < 2; mf++) {
#pragma unroll
        for (int nf = 0; nf < 8; nf++) {
            const int cc = wn + nf * 8 + (lid & 3) * 2;    // tile col (even)
            const int n = n0 + cc;
            const int r = wm + mf * 16 + (lid >> 2);       // tile row
            float v0 = acc[mf][nf][0] * kscale;
            float v1 = acc[mf][nf][1] * kscale;
            float v2 = acc[mf][nf][2] * kscale;
            float v3 = acc[mf][nf][3] * kscale;
            if (MODE != 0) {
                float b0 = bias[n], b1 = bias[n + 1];
                v0 += b0; v1 += b1; v2 += b0; v3 += b1;
            }
            const long long m = m0 + r;
            if (MODE == 0) {
                float* p = Cf + ((long long)blockIdx.z * 2048 + m) * 2048 + n;
                *(float2*)p = make_float2(v0, v1);
                *(float2*)(p + 8 * 2048) = make_float2(v2, v3);
            } else if (MODE == 1) {
                float* p = Cf + m * 256 + n;
                *(float2*)p = make_float2(v0, v1);
                *(float2*)(p + 8 * 256) = make_float2(v2, v3);
            } else {
                __nv_bfloat16 h0 = __float2bfloat16(v0);
                __nv_bfloat16 l0 = __float2bfloat16(v0 - __bfloat162float(h0));
                __nv_bfloat16 h1 = __float2bfloat16(v1);
                __nv_bfloat16 l1 = __float2bfloat16(v1 - __bfloat162float(h1));
                __nv_bfloat16 h2 = __float2bfloat16(v2);
                __nv_bfloat16 l2 = __float2bfloat16(v2 - __bfloat162float(h2));
                __nv_bfloat16 h3 = __float2bfloat16(v3);
                __nv_bfloat16 l3 = __float2bfloat16(v3 - __bfloat162float(h3));
                __nv_bfloat16* o0 = Cb + m * KTOT;
                __nv_bfloat16* o1 = Cb + (m + 8) * KTOT;
                __nv_bfloat162 hh0 = {h0, h1}, ll0 = {l0, l1};
                __nv_bfloat162 hh1 = {h2, h3}, ll1 = {l2, l3};
                *(__nv_bfloat162*)(o0 + n) = hh0;
                *(__nv_bfloat162*)(o1 + n) = hh1;
                if (MODE == 2) {   // A-pattern [hi, hi, lo]
                    *(__nv_bfloat162*)(o0 + n + 256) = hh0;
                    *(__nv_bfloat162*)(o0 + n + 512) = ll0;
                    *(__nv_bfloat162*)(o1 + n + 256) = hh1;
                    *(__nv_bfloat162*)(o1 + n + 512) = ll1;
                } else {           // B-pattern [hi, lo, hi]
                    *(__nv_bfloat162*)(o0 + n + 256) = ll0;
                    *(__nv_bfloat162*)(o0 + n + 512) = hh0;
                    *(__nv_bfloat162*)(o1 + n + 256) = ll1;
                    *(__nv_bfloat162*)(o1 + n + 512) = hh1;
                }
            }
        }
    }
}

// ---------------------------------------------------------------------------
// Online single-pass row softmax stats: max + 1/sumexp. Block per row.
// ---------------------------------------------------------------------------
__global__ void row_stats_kernel() {
    const int r = blockIdx.x;
    const float4* e = (const float4*)(g_energy + (long long)r * 2048);
    const int t = threadIdx.x;                   // 256 threads, 2 float4 each
    float4 u = e[t], w = e[t + 256];
    float m = fmaxf(fmaxf(fmaxf(u.x, u.y), fmaxf(u.z, u.w)),
                    fmaxf(fmaxf(w.x, w.y), fmaxf(w.z, w.w)));
    float s = __expf(u.x - m) + __expf(u.y - m) + __expf(u.z - m) + __expf(u.w - m)
            + __expf(w.x - m) + __expf(w.y - m) + __expf(w.z - m) + __expf(w.w - m);

    __shared__ float rm[256], rs[256];
    rm[t] = m; rs[t] = s;
    __syncthreads();
    for (int st = 128; st > 0; st >>= 1) {
        if (t < st) {
            float m2 = rm[t + st], s2 = rs[t + st];
            float mm = fmaxf(rm[t], m2);
            rs[t] = rs[t] * __expf(rm[t] - mm) + s2 * __expf(m2 - mm);
            rm[t] = mm;
        }
        __syncthreads();
    }
    if (t == 0) { g_mx[r] = rm[0]; g_is[r] = 1.0f / rs[0]; }
}

// ---------------------------------------------------------------------------
// Column sums: w[b,k] = sum_q exp(e[q,k]-mx[q])*is[q].  float4 over k.
// ---------------------------------------------------------------------------
__global__ void colsum_kernel() {
    const int b = blockIdx.x;
    const int k = blockIdx.y * 1024 + threadIdx.x * 4;
    const float* e  = g_energy + (long long)b * 2048 * 2048 + k;
    const float* mx = g_mx + b * 2048;
    const float* is = g_is + b * 2048;
    float4 acc = make_float4(0.f, 0.f, 0.f, 0.f);
#pragma unroll 4
    for (int q = 0; q < 2048; q++) {
        float4 v = *(const float4*)(e + (long long)q * 2048);
        float w = is[q];
        float m = mx[q];
        acc.x += __expf(v.x - m) * w;
        acc.y += __expf(v.y - m) * w;
        acc.z += __expf(v.z - m) * w;
        acc.w += __expf(v.w - m) * w;
    }
    *(float4*)(g_w + b * 2048 + k) = acc;
}

// ---------------------------------------------------------------------------
// Final contraction: out[b,d] = sum_k w[b,k] * v[b,k,d]
// ---------------------------------------------------------------------------
__global__ void out_kernel(float* __restrict__ out) {
    const int b = blockIdx.x;
    const int d = threadIdx.x;
    const float* w = g_w + b * 2048;
    const float* v = g_v + (long long)b * 2048 * 256 + d;
    float acc = 0.0f;
#pragma unroll 8
    for (int kk = 0; kk < 2048; kk++)
        acc = fmaf(w[kk], v[(long long)kk * 256], acc);
    out[b * 256 + d] = acc;
}

// ---------------------------------------------------------------------------
extern "C" void kernel_launch(void* const* d_in, const int* in_sizes, int n_in,
                              void* d_out, int out_size) {
    (void)in_sizes; (void)n_in; (void)out_size;
    const float* x  = (const float*)d_in[0];
    const float* Wq = (const float*)d_in[1];
    const float* bq = (const float*)d_in[2];
    const float* Wk = (const float*)d_in[3];
    const float* bk = (const float*)d_in[4];
    const float* Wv = (const float*)d_in[5];
    const float* bv = (const float*)d_in[6];
    float* out = (float*)d_out;

    __nv_bfloat16 *pxs, *pwtq, *pwtk, *pwtv, *pqs, *pks;
    float *pv, *pe;
    cudaGetSymbolAddress((void**)&pxs, g_xs);
    cudaGetSymbolAddress((void**)&pwtq, g_wtq);
    cudaGetSymbolAddress((void**)&pwtk, g_wtk);
    cudaGetSymbolAddress((void**)&pwtv, g_wtv);
    cudaGetSymbolAddress((void**)&pqs, g_qs);
    cudaGetSymbolAddress((void**)&pks, g_ks);
    cudaGetSymbolAddress((void**)&pv, g_v);
    cudaGetSymbolAddress((void**)&pe, g_energy);

    // 1) splits
    split_x_kernel<<<32768, 256>>>(x);
    split_w_kernel<<<256, 256>>>(Wq, pwtq);
    split_w_kernel<<<256, 256>>>(Wk, pwtk);
    split_w_kernel<<<256, 256>>>(Wv, pwtv);

    // 2) projections: M=32768, N=256 (2 tiles), K'=768
    dim3 gproj(2, 256, 1);
    hmma_gemm<2><<<gproj, 256>>>(pxs, pwtq, bq, nullptr, pqs, 0, 0, 1.0f);
    hmma_gemm<3><<<gproj, 256>>>(pxs, pwtk, bk, nullptr, pks, 0, 0, 1.0f);
    hmma_gemm<1><<<gproj, 256>>>(pxs, pwtv, bv, pv, nullptr, 0, 0, 1.0f);

    // 3) energy = q k^T / 16, batched
    dim3 gen(16, 16, 16);
    hmma_gemm<0><<<gen, 256>>>(pqs, pks, nullptr, pe, nullptr,
                               (long long)2048 * KTOT, (long long)2048 * KTOT,
                               0.0625f);

    // 4-6) stats, column sums, final contraction
    row_stats_kernel<<<32768, 256>>>();
    colsum_kernel<<<dim3(16, 2), 256>>>();
    out_kernel<<<16, 256>>>(out);
}

// round 6
// speedup vs baseline: 2.4409x; 1.8186x over previous
#include <cuda_runtime.h>
#include <cuda_fp16.h>
#include <cstdint>

// ---------------------------------------------------------------------------
// Attention_49048526520431 (GB300 sm_103a via compute_103 family target).
//   out[b,d] = sum_k (sum_q softmax(q k^T /16)[q,k]) * v[b,k,d]
// B=16, S=2048, D=256 fp32.
//
// All GEMMs: mma.sync.m16n8k16 fp16 (family-portable), fp32 accumulate.
// Projections: 3-term fp16 split, K'=768 (error ~2^-22).
// Energy:      2-term fp16 split, K'=512:
//   A'=[q_hi|q_lo], B'=[k_hi|k_hi]  ->  q·k_hi  (missing q·k_lo ~2e-4 abs)
// Energy stored fp16 (halves stats-pass traffic).
// ---------------------------------------------------------------------------

#define KP 768                 /* projection K' */
#define KE 512                 /* energy K' */
#define KPAD 72                /* smem row stride in halves (144B) */
#define SMEM_BYTES (4 * 128 * KPAD * 2)   /* 73728: A0,A1,B0,B1 */

__device__ __half g_xs[32768 * KP];        // x split, A-pattern [hi,hi,lo]
__device__ __half g_wtq[256 * KP];         // W^T split, B-pattern [hi,lo,hi]
__device__ __half g_wtk[256 * KP];
__device__ __half g_wtv[256 * KP];
__device__ __half g_qs[16 * 2048 * KE];    // q split [hi|lo]
__device__ __half g_ks[16 * 2048 * KE];    // k split [hi|hi]
__device__ float  g_v[16 * 2048 * 256];
__device__ __half g_energy[67108864];      // 16 * 2048 * 2048 fp16
__device__ float  g_mx[16 * 2048];
__device__ float  g_is[16 * 2048];
__device__ float  g_wp[128 * 2048];        // colsum partials (16 b x 8 qc)
__device__ float  g_w[16 * 2048];

// ----------------------------- PTX helpers ---------------------------------
__device__ __forceinline__ uint32_t smem_u32(const void* p) {
    uint32_t a;
    asm("{ .reg .u64 t; cvta.to.shared.u64 t, %1; cvt.u32.u64 %0, t; }" : "=r"(a) : "l"(p));
    return a;
}
__device__ __forceinline__ void cp16(uint32_t s, const void* g) {
    asm volatile("cp.async.cg.shared.global [%0], [%1], 16;" :: "r"(s), "l"(g));
}
#define CP_COMMIT() asm volatile("cp.async.commit_group;" ::: "memory")
#define CP_WAIT(n)  asm volatile("cp.async.wait_group %0;" :: "n"(n) : "memory")

__device__ __forceinline__ void ldmx4(uint32_t a, uint32_t& r0, uint32_t& r1,
                                      uint32_t& r2, uint32_t& r3) {
    asm volatile("ldmatrix.sync.aligned.m8n8.x4.shared.b16 {%0,%1,%2,%3}, [%4];"
                 : "=r"(r0), "=r"(r1), "=r"(r2), "=r"(r3) : "r"(a));
}
__device__ __forceinline__ void mma16816(float* c, uint32_t a0, uint32_t a1,
                                         uint32_t a2, uint32_t a3,
                                         uint32_t b0, uint32_t b1) {
    asm volatile(
        "mma.sync.aligned.m16n8k16.row.col.f32.f16.f16.f32 "
        "{%0,%1,%2,%3}, {%4,%5,%6,%7}, {%8,%9}, {%0,%1,%2,%3};"
        : "+f"(c[0]), "+f"(c[1]), "+f"(c[2]), "+f"(c[3])
        : "r"(a0), "r"(a1), "r"(a2), "r"(a3), "r"(b0), "r"(b1));
}

// ---------------------------------------------------------------------------
// Split prep kernels (fp16)
// ---------------------------------------------------------------------------
__global__ void split_x_kernel(const float* __restrict__ x) {
    long long i = (long long)blockIdx.x * 256 + threadIdx.x;
    long long row = i >> 8;
    int col = (int)(i & 255);
    float v = x[i];
    __half hi = __float2half(v);
    __half lo = __float2half(v - __half2float(hi));
    __half* o = g_xs + row * KP;
    o[col] = hi; o[col + 256] = hi; o[col + 512] = lo;          // A-pattern
}

__global__ void split_w_kernel(const float* __restrict__ W, __half* __restrict__ Wt) {
    int n = blockIdx.x;
    int k = threadIdx.x;
    float v = W[k * 256 + n];                                   // transpose
    __half hi = __float2half(v);
    __half lo = __float2half(v - __half2float(hi));
    __half* o = Wt + n * KP;
    o[k] = hi; o[k + 256] = lo; o[k + 512] = hi;                // B-pattern
}

// ---------------------------------------------------------------------------
// fp16 HMMA GEMM: D[m,n] = scale * sum_k A[m,k]*B[n,k] (+bias).
// 128x128 CTA tile, 4 warps (2x2) of 64x64, BK=64, double-buffered cp.async.
// MODE 0: energy -> g_energy fp16 (batched z). MODE 1: v proj -> g_v fp32.
// MODE 2: q proj -> g_qs [hi|lo].  MODE 3: k proj -> g_ks [hi|hi].
// ---------------------------------------------------------------------------
template <int MODE, int KLEN>
__global__ __launch_bounds__(128, 2) void hmma_gemm(
    const __half* __restrict__ A, const __half* __restrict__ B,
    const float* __restrict__ bias, float* __restrict__ Cf,
    __half* __restrict__ Ch, long long strideA, long long strideB, float scale)
{
    extern __shared__ __align__(128) unsigned char dyn[];
    __half* sA0 = (__half*)dyn;
    __half* sA1 = sA0 + 128 * KPAD;
    __half* sB0 = sA1 + 128 * KPAD;
    __half* sB1 = sB0 + 128 * KPAD;

    const int tid = threadIdx.x;
    const int lid = tid & 31;
    const int wid = tid >> 5;
    const int wm = (wid & 1) * 64;
    const int wn = (wid >> 1) * 64;
    const int n0 = blockIdx.x * 128;
    const int m0 = blockIdx.y * 128;
    A += (long long)blockIdx.z * strideA;
    B += (long long)blockIdx.z * strideB;

    const int lr = tid >> 3;             // 0..15 base row for loads
    const int lc = (tid & 7) * 8;        // 16B-unit col (halves)

    float acc[4][8][4];
#pragma unroll
    for (int i = 0; i < 4; i++)
#pragma unroll
        for (int j = 0; j < 8; j++)
#pragma unroll
            for (int q = 0; q < 4; q++) acc[i][j][q] = 0.0f;

    uint32_t sAb[2] = { smem_u32(sA0), smem_u32(sA1) };
    uint32_t sBb[2] = { smem_u32(sB0), smem_u32(sB1) };

    const int xrow = lid & 15;
    const int xcol = (lid >> 4) * 8;
    const int NC = KLEN / 64;

    auto load_chunk = [&](int c) {
        const int k0 = c * 64;
        const int b = c & 1;
#pragma unroll
        for (int i = 0; i < 8; i++) {
            int r = lr + i * 16;
            cp16(sAb[b] + (r * KPAD + lc) * 2, A + (long long)(m0 + r) * KLEN + k0 + lc);
            cp16(sBb[b] + (r * KPAD + lc) * 2, B + (long long)(n0 + r) * KLEN + k0 + lc);
        }
    };

    load_chunk(0);
    CP_COMMIT();

    for (int c = 0; c < NC; c++) {
        if (c + 1 < NC) { load_chunk(c + 1); CP_COMMIT(); CP_WAIT(1); }
        else CP_WAIT(0);
        __syncthreads();
        const int b = c & 1;
#pragma unroll
        for (int kf = 0; kf < 4; kf++) {
            uint32_t a[4][4];
#pragma unroll
            for (int mf = 0; mf < 4; mf++)
                ldmx4(sAb[b] + ((wm + mf * 16 + xrow) * KPAD + kf * 16 + xcol) * 2,
                      a[mf][0], a[mf][1], a[mf][2], a[mf][3]);
            uint32_t bp[8][2];
#pragma unroll
            for (int np = 0; np < 4; np++) {
                uint32_t r0, r1, r2, r3;
                ldmx4(sBb[b] + ((wn + np * 16 + xrow) * KPAD + kf * 16 + xcol) * 2,
                      r0, r1, r2, r3);
                bp[np * 2 + 0][0] = r0; bp[np * 2 + 0][1] = r2;
                bp[np * 2 + 1][0] = r1; bp[np * 2 + 1][1] = r3;
            }
#pragma unroll
            for (int mf = 0; mf < 4; mf++)
#pragma unroll
                for (int nf = 0; nf < 8; nf++)
                    mma16816(acc[mf][nf], a[mf][0], a[mf][1], a[mf][2], a[mf][3],
                             bp[nf][0], bp[nf][1]);
        }
        __syncthreads();
    }

    // ------------------------------ epilogue -------------------------------
#pragma unroll
    for (int mf = 0; mf < 4; mf++) {
#pragma unroll
        for (int nf = 0; nf < 8; nf++) {
            const int cc = wn + nf * 8 + (lid & 3) * 2;
            const int n = n0 + cc;
            const int r = wm + mf * 16 + (lid >> 2);
            float v0 = acc[mf][nf][0] * scale;
            float v1 = acc[mf][nf][1] * scale;
            float v2 = acc[mf][nf][2] * scale;
            float v3 = acc[mf][nf][3] * scale;
            if (MODE != 0) {
                float b0 = bias[n], b1 = bias[n + 1];
                v0 += b0; v1 += b1; v2 += b0; v3 += b1;
            }
            const long long m = m0 + r;
            if (MODE == 0) {
                __half* p = Ch + ((long long)blockIdx.z * 2048 + m) * 2048 + n;
                *(__half2*)p = __halves2half2(__float2half(v0), __float2half(v1));
                *(__half2*)(p + 8 * 2048) = __halves2half2(__float2half(v2), __float2half(v3));
            } else if (MODE == 1) {
                float* p = Cf + m * 256 + n;
                *(float2*)p = make_float2(v0, v1);
                *(float2*)(p + 8 * 256) = make_float2(v2, v3);
            } else {
                __half h0 = __float2half(v0), h1 = __float2half(v1);
                __half h2 = __float2half(v2), h3 = __float2half(v3);
                __half* o0 = Ch + m * KE;
                __half* o1 = Ch + (m + 8) * KE;
                *(__half2*)(o0 + n) = __halves2half2(h0, h1);
                *(__half2*)(o1 + n) = __halves2half2(h2, h3);
                if (MODE == 2) {   // lo in second half
                    __half l0 = __float2half(v0 - __half2float(h0));
                    __half l1 = __float2half(v1 - __half2float(h1));
                    __half l2 = __float2half(v2 - __half2float(h2));
                    __half l3 = __float2half(v3 - __half2float(h3));
                    *(__half2*)(o0 + n + 256) = __halves2half2(l0, l1);
                    *(__half2*)(o1 + n + 256) = __halves2half2(l2, l3);
                } else {           // hi duplicated
                    *(__half2*)(o0 + n + 256) = __halves2half2(h0, h1);
                    *(__half2*)(o1 + n + 256) = __halves2half2(h2, h3);
                }
            }
        }
    }
}

// ---------------------------------------------------------------------------
// Row softmax stats over fp16 energy: one block per row, 8 halves per thread.
// ---------------------------------------------------------------------------
__global__ void row_stats_kernel() {
    const int r = blockIdx.x;
    const __half* e = g_energy + (long long)r * 2048;
    const int t = threadIdx.x;
    uint4 u = *(const uint4*)(e + t * 8);
    float f[8];
    {
        __half2* hp = (__half2*)&u;
#pragma unroll
        for (int i = 0; i < 4; i++) {
            float2 p = __half22float2(hp[i]);
            f[i * 2] = p.x; f[i * 2 + 1] = p.y;
        }
    }
    float m = f[0];
#pragma unroll
    for (int i = 1; i < 8; i++) m = fmaxf(m, f[i]);
    float s = 0.0f;
#pragma unroll
    for (int i = 0; i < 8; i++) s += __expf(f[i] - m);

    __shared__ float rm[256], rs[256];
    rm[t] = m; rs[t] = s;
    __syncthreads();
    for (int st = 128; st > 0; st >>= 1) {
        if (t < st) {
            float m2 = rm[t + st], s2 = rs[t + st];
            float mm = fmaxf(rm[t], m2);
            rs[t] = rs[t] * __expf(rm[t] - mm) + s2 * __expf(m2 - mm);
            rm[t] = mm;
        }
        __syncthreads();
    }
    if (t == 0) { g_mx[r] = rm[0]; g_is[r] = 1.0f / rs[0]; }
}

// ---------------------------------------------------------------------------
// Partial column sums: block (b, qc) sums 256 q-rows into g_wp.
// ---------------------------------------------------------------------------
__global__ void colsum_kernel() {
    const int b = blockIdx.x;
    const int qc = blockIdx.y;
    const int k0 = threadIdx.x * 8;
    const __half* e = g_energy + ((long long)b * 2048) * 2048 + k0;
    const float* mx = g_mx + b * 2048;
    const float* is = g_is + b * 2048;
    float acc[8];
#pragma unroll
    for (int i = 0; i < 8; i++) acc[i] = 0.0f;
    const int q0 = qc * 256;
    for (int q = q0; q < q0 + 256; q++) {
        uint4 u = *(const uint4*)(e + (long long)q * 2048);
        float m = mx[q], w = is[q];
        __half2* hp = (__half2*)&u;
#pragma unroll
        for (int i = 0; i < 4; i++) {
            float2 p = __half22float2(hp[i]);
            acc[i * 2]     += __expf(p.x - m) * w;
            acc[i * 2 + 1] += __expf(p.y - m) * w;
        }
    }
    float* o = g_wp + ((long long)b * 8 + qc) * 2048 + k0;
#pragma unroll
    for (int i = 0; i < 8; i++) o[i] = acc[i];
}

__global__ void wreduce_kernel() {
    const int i = blockIdx.x * 256 + threadIdx.x;     // 0..32767
    const int b = i >> 11, k = i & 2047;
    float s = 0.0f;
#pragma unroll
    for (int j = 0; j < 8; j++) s += g_wp[((long long)b * 8 + j) * 2048 + k];
    g_w[i] = s;
}

// ---------------------------------------------------------------------------
// Final contraction: out[b,d] = sum_k w[b,k] * v[b,k,d]
// ---------------------------------------------------------------------------
__global__ void out_kernel(float* __restrict__ out) {
    const int b = blockIdx.x;
    const int d = threadIdx.x;
    const float* w = g_w + b * 2048;
    const float* v = g_v + (long long)b * 2048 * 256 + d;
    float acc = 0.0f;
#pragma unroll 8
    for (int kk = 0; kk < 2048; kk++)
        acc = fmaf(w[kk], v[(long long)kk * 256], acc);
    out[b * 256 + d] = acc;
}

// ---------------------------------------------------------------------------
extern "C" void kernel_launch(void* const* d_in, const int* in_sizes, int n_in,
                              void* d_out, int out_size) {
    (void)in_sizes; (void)n_in; (void)out_size;
    const float* x  = (const float*)d_in[0];
    const float* Wq = (const float*)d_in[1];
    const float* bq = (const float*)d_in[2];
    const float* Wk = (const float*)d_in[3];
    const float* bk = (const float*)d_in[4];
    const float* Wv = (const float*)d_in[5];
    const float* bv = (const float*)d_in[6];
    float* out = (float*)d_out;

    __half *pxs, *pwtq, *pwtk, *pwtv, *pqs, *pks, *pe;
    float *pv;
    cudaGetSymbolAddress((void**)&pxs, g_xs);
    cudaGetSymbolAddress((void**)&pwtq, g_wtq);
    cudaGetSymbolAddress((void**)&pwtk, g_wtk);
    cudaGetSymbolAddress((void**)&pwtv, g_wtv);
    cudaGetSymbolAddress((void**)&pqs, g_qs);
    cudaGetSymbolAddress((void**)&pks, g_ks);
    cudaGetSymbolAddress((void**)&pv, g_v);
    cudaGetSymbolAddress((void**)&pe, g_energy);

    static int attr_done = 0;
    if (!attr_done) {
        cudaFuncSetAttribute(hmma_gemm<0, KE>, cudaFuncAttributeMaxDynamicSharedMemorySize, SMEM_BYTES);
        cudaFuncSetAttribute(hmma_gemm<1, KP>, cudaFuncAttributeMaxDynamicSharedMemorySize, SMEM_BYTES);
        cudaFuncSetAttribute(hmma_gemm<2, KP>, cudaFuncAttributeMaxDynamicSharedMemorySize, SMEM_BYTES);
        cudaFuncSetAttribute(hmma_gemm<3, KP>, cudaFuncAttributeMaxDynamicSharedMemorySize, SMEM_BYTES);
        attr_done = 1;
    }

    // 1) splits
    split_x_kernel<<<32768, 256>>>(x);
    split_w_kernel<<<256, 256>>>(Wq, pwtq);
    split_w_kernel<<<256, 256>>>(Wk, pwtk);
    split_w_kernel<<<256, 256>>>(Wv, pwtv);

    // 2) projections: M=32768, N=256 (2 tiles), K'=768
    dim3 gproj(2, 256, 1);
    hmma_gemm<2, KP><<<gproj, 128, SMEM_BYTES>>>(pxs, pwtq, bq, nullptr, pqs, 0, 0, 1.0f);
    hmma_gemm<3, KP><<<gproj, 128, SMEM_BYTES>>>(pxs, pwtk, bk, nullptr, pks, 0, 0, 1.0f);
    hmma_gemm<1, KP><<<gproj, 128, SMEM_BYTES>>>(pxs, pwtv, bv, pv, nullptr, 0, 0, 1.0f);

    // 3) energy = q k^T / 16, batched, K'=512
    dim3 gen(16, 16, 16);
    hmma_gemm<0, KE><<<gen, 128, SMEM_BYTES>>>(pqs, pks, nullptr, nullptr, pe,
                                               (long long)2048 * KE, (long long)2048 * KE,
                                               0.0625f);

    // 4-7) stats, partial colsums, reduce, final contraction
    row_stats_kernel<<<32768, 256>>>();
    colsum_kernel<<<dim3(16, 8), 256>>>();
    wreduce_kernel<<<128, 256>>>();
    out_kernel<<<16, 256>>>(out);
}

// round 7
// speedup vs baseline: 4.9973x; 2.0473x over previous
#include <cuda_runtime.h>
#include <cuda_fp16.h>
#include <cstdint>

// ---------------------------------------------------------------------------
// Attention_49048526520431 (GB300 sm_103a via compute_103 family target).
//   out[b,d] = sum_k (sum_q softmax(q k^T /16)[q,k]) * v[b,k,d]
// B=16, S=2048, D=256 fp32.
//
// GEMMs: mma.sync.m16n8k16 fp16, fp32 accumulate.
//  x  split layout: [x_hi | x_lo | x_hi]   (768)
//  W  split layout: [W_hi | W_hi | W_lo]   (768)
//  q,k proj: K=512 prefix -> x_hi·W_hi + x_lo·W_hi   (2-term)
//  v   proj: K=768 full   -> + x_hi·W_lo             (3-term)
//  energy  : K=256 plain  -> q_hi · k_hi  (fp16 out; storage err dominates)
// Softmax stats + column sums fused into ONE pass over energy.
// ---------------------------------------------------------------------------

#define KSPLIT 768
#define KPAD 72                /* smem row stride in halves (144B) */
#define SMEM_BYTES (4 * 128 * KPAD * 2)   /* 73728: A0,A1,B0,B1 */

__device__ __half g_xs[32768 * KSPLIT];    // [hi | lo | hi]
__device__ __half g_wtq[256 * KSPLIT];     // [hi | hi | lo]
__device__ __half g_wtk[256 * KSPLIT];
__device__ __half g_wtv[256 * KSPLIT];
__device__ __half g_qs[16 * 2048 * 256];   // q hi
__device__ __half g_ks[16 * 2048 * 256];   // k hi
__device__ float  g_v[16 * 2048 * 256];
__device__ __half g_energy[67108864];      // 16 * 2048 * 2048 fp16
__device__ float  g_wp[128 * 2048];        // colsum partials (b x 8 qc)
__device__ float  g_w[16 * 2048];
__device__ float  g_op[128 * 256];         // out partials (b x 8 kc)

// ----------------------------- PTX helpers ---------------------------------
__device__ __forceinline__ uint32_t smem_u32(const void* p) {
    uint32_t a;
    asm("{ .reg .u64 t; cvta.to.shared.u64 t, %1; cvt.u32.u64 %0, t; }" : "=r"(a) : "l"(p));
    return a;
}
__device__ __forceinline__ void cp16(uint32_t s, const void* g) {
    asm volatile("cp.async.cg.shared.global [%0], [%1], 16;" :: "r"(s), "l"(g));
}
#define CP_COMMIT() asm volatile("cp.async.commit_group;" ::: "memory")
#define CP_WAIT(n)  asm volatile("cp.async.wait_group %0;" :: "n"(n) : "memory")

__device__ __forceinline__ void ldmx4(uint32_t a, uint32_t& r0, uint32_t& r1,
                                      uint32_t& r2, uint32_t& r3) {
    asm volatile("ldmatrix.sync.aligned.m8n8.x4.shared.b16 {%0,%1,%2,%3}, [%4];"
                 : "=r"(r0), "=r"(r1), "=r"(r2), "=r"(r3) : "r"(a));
}
__device__ __forceinline__ void mma16816(float* c, uint32_t a0, uint32_t a1,
                                         uint32_t a2, uint32_t a3,
                                         uint32_t b0, uint32_t b1) {
    asm volatile(
        "mma.sync.aligned.m16n8k16.row.col.f32.f16.f16.f32 "
        "{%0,%1,%2,%3}, {%4,%5,%6,%7}, {%8,%9}, {%0,%1,%2,%3};"
        : "+f"(c[0]), "+f"(c[1]), "+f"(c[2]), "+f"(c[3])
        : "r"(a0), "r"(a1), "r"(a2), "r"(a3), "r"(b0), "r"(b1));
}

// ---------------------------------------------------------------------------
// Split prep
// ---------------------------------------------------------------------------
__global__ void split_x_kernel(const float* __restrict__ x) {
    long long i = (long long)blockIdx.x * 256 + threadIdx.x;
    long long row = i >> 8;
    int col = (int)(i & 255);
    float v = x[i];
    __half hi = __float2half(v);
    __half lo = __float2half(v - __half2float(hi));
    __half* o = g_xs + row * KSPLIT;
    o[col] = hi; o[col + 256] = lo; o[col + 512] = hi;          // [hi|lo|hi]
}

__global__ void split_w_kernel(const float* __restrict__ W, __half* __restrict__ Wt) {
    int n = blockIdx.x;
    int k = threadIdx.x;
    float v = W[k * 256 + n];                                   // transpose
    __half hi = __float2half(v);
    __half lo = __float2half(v - __half2float(hi));
    __half* o = Wt + n * KSPLIT;
    o[k] = hi; o[k + 256] = hi; o[k + 512] = lo;                // [hi|hi|lo]
}

// ---------------------------------------------------------------------------
// fp16 HMMA GEMM: D[m,n] = scale * sum_k A[m,k]*B[n,k] (+bias).
// 128x128 CTA tile, 4 warps (2x2) of 64x64, BK=64, double-buffered cp.async.
// MODE 0: energy -> Ch fp16 stride 2048 (batched z).
// MODE 1: v -> Cf fp32 stride 256 (+bias).
// MODE 2: q/k -> Ch fp16 stride 256 (+bias).
// ---------------------------------------------------------------------------
template <int MODE, int KLEN>
__global__ __launch_bounds__(128, 2) void hmma_gemm(
    const __half* __restrict__ A, const __half* __restrict__ B,
    const float* __restrict__ bias, float* __restrict__ Cf,
    __half* __restrict__ Ch, long long lda, long long ldb,
    long long strideA, long long strideB, float scale)
{
    extern __shared__ __align__(128) unsigned char dyn[];
    __half* sA0 = (__half*)dyn;
    __half* sA1 = sA0 + 128 * KPAD;
    __half* sB0 = sA1 + 128 * KPAD;
    __half* sB1 = sB0 + 128 * KPAD;

    const int tid = threadIdx.x;
    const int lid = tid & 31;
    const int wid = tid >> 5;
    const int wm = (wid & 1) * 64;
    const int wn = (wid >> 1) * 64;
    const int n0 = blockIdx.x * 128;
    const int m0 = blockIdx.y * 128;
    A += (long long)blockIdx.z * strideA;
    B += (long long)blockIdx.z * strideB;

    const int lr = tid >> 3;             // 0..15 base row for loads
    const int lc = (tid & 7) * 8;        // col in halves

    float acc[4][8][4];
#pragma unroll
    for (int i = 0; i < 4; i++)
#pragma unroll
        for (int j = 0; j < 8; j++)
#pragma unroll
            for (int q = 0; q < 4; q++) acc[i][j][q] = 0.0f;

    uint32_t sAb[2] = { smem_u32(sA0), smem_u32(sA1) };
    uint32_t sBb[2] = { smem_u32(sB0), smem_u32(sB1) };

    const int xrow = lid & 15;
    const int xcol = (lid >> 4) * 8;
    const int NC = KLEN / 64;

    auto load_chunk = [&](int c) {
        const int k0 = c * 64;
        const int b = c & 1;
#pragma unroll
        for (int i = 0; i < 8; i++) {
            int r = lr + i * 16;
            cp16(sAb[b] + (r * KPAD + lc) * 2, A + (long long)(m0 + r) * lda + k0 + lc);
            cp16(sBb[b] + (r * KPAD + lc) * 2, B + (long long)(n0 + r) * ldb + k0 + lc);
        }
    };

    load_chunk(0);
    CP_COMMIT();

    for (int c = 0; c < NC; c++) {
        if (c + 1 < NC) { load_chunk(c + 1); CP_COMMIT(); CP_WAIT(1); }
        else CP_WAIT(0);
        __syncthreads();
        const int b = c & 1;
#pragma unroll
        for (int kf = 0; kf < 4; kf++) {
            uint32_t a[4][4];
#pragma unroll
            for (int mf = 0; mf < 4; mf++)
                ldmx4(sAb[b] + ((wm + mf * 16 + xrow) * KPAD + kf * 16 + xcol) * 2,
                      a[mf][0], a[mf][1], a[mf][2], a[mf][3]);
            uint32_t bp[8][2];
#pragma unroll
            for (int np = 0; np < 4; np++) {
                uint32_t r0, r1, r2, r3;
                ldmx4(sBb[b] + ((wn + np * 16 + xrow) * KPAD + kf * 16 + xcol) * 2,
                      r0, r1, r2, r3);
                bp[np * 2 + 0][0] = r0; bp[np * 2 + 0][1] = r2;
                bp[np * 2 + 1][0] = r1; bp[np * 2 + 1][1] = r3;
            }
#pragma unroll
            for (int mf = 0; mf < 4; mf++)
#pragma unroll
                for (int nf = 0; nf < 8; nf++)
                    mma16816(acc[mf][nf], a[mf][0], a[mf][1], a[mf][2], a[mf][3],
                             bp[nf][0], bp[nf][1]);
        }
        __syncthreads();
    }

    // ------------------------------ epilogue -------------------------------
#pragma unroll
    for (int mf = 0; mf < 4; mf++) {
#pragma unroll
        for (int nf = 0; nf < 8; nf++) {
            const int cc = wn + nf * 8 + (lid & 3) * 2;
            const int n = n0 + cc;
            const int r = wm + mf * 16 + (lid >> 2);
            float v0 = acc[mf][nf][0] * scale;
            float v1 = acc[mf][nf][1] * scale;
            float v2 = acc[mf][nf][2] * scale;
            float v3 = acc[mf][nf][3] * scale;
            if (MODE != 0) {
                float b0 = bias[n], b1 = bias[n + 1];
                v0 += b0; v1 += b1; v2 += b0; v3 += b1;
            }
            const long long m = m0 + r;
            if (MODE == 0) {
                __half* p = Ch + ((long long)blockIdx.z * 2048 + m) * 2048 + n;
                *(__half2*)p = __halves2half2(__float2half(v0), __float2half(v1));
                *(__half2*)(p + 8 * 2048) = __halves2half2(__float2half(v2), __float2half(v3));
            } else if (MODE == 1) {
                float* p = Cf + m * 256 + n;
                *(float2*)p = make_float2(v0, v1);
                *(float2*)(p + 8 * 256) = make_float2(v2, v3);
            } else {
                __half* p = Ch + m * 256 + n;
                *(__half2*)p = __halves2half2(__float2half(v0), __float2half(v1));
                *(__half2*)(p + 8 * 256) = __halves2half2(__float2half(v2), __float2half(v3));
            }
        }
    }
}

// ---------------------------------------------------------------------------
// Fused softmax colsum: one pass over energy.
// Block = (b, qc): 8 warps, one warp per row, 32 rows/warp.
// Lane l owns cols {(l+32i)*8+j : i<8, j<8}. Per row: warp-shfl max, exp once
// (cached packed fp16 in the load regs), warp-shfl sum, scale into col accs.
// ---------------------------------------------------------------------------
__global__ __launch_bounds__(256) void colsum_fused_kernel() {
    const int b = blockIdx.x;
    const int qc = blockIdx.y;
    const int tid = threadIdx.x;
    const int wid = tid >> 5;
    const int lid = tid & 31;

    __shared__ float sacc[2048];
    for (int i = tid; i < 2048; i += 256) sacc[i] = 0.0f;
    __syncthreads();

    float acc[8][8];
#pragma unroll
    for (int i = 0; i < 8; i++)
#pragma unroll
        for (int j = 0; j < 8; j++) acc[i][j] = 0.0f;

    const __half* ebase = g_energy + ((long long)(b * 2048 + qc * 256)) * 2048;

    for (int r = wid; r < 256; r += 8) {
        const uint4* rp = (const uint4*)(ebase + (long long)r * 2048);
        uint4 u[8];
#pragma unroll
        for (int i = 0; i < 8; i++) u[i] = rp[lid + 32 * i];

        // row max
        float m = -3.4e38f;
#pragma unroll
        for (int i = 0; i < 8; i++) {
            __half2* hp = (__half2*)&u[i];
#pragma unroll
            for (int j = 0; j < 4; j++) {
                float2 p = __half22float2(hp[j]);
                m = fmaxf(m, fmaxf(p.x, p.y));
            }
        }
#pragma unroll
        for (int o = 16; o > 0; o >>= 1)
            m = fmaxf(m, __shfl_xor_sync(0xFFFFFFFFu, m, o));

        // exp once, cache as fp16 in place, accumulate row sum
        float s = 0.0f;
#pragma unroll
        for (int i = 0; i < 8; i++) {
            __half2* hp = (__half2*)&u[i];
#pragma unroll
            for (int j = 0; j < 4; j++) {
                float2 p = __half22float2(hp[j]);
                float e0 = __expf(p.x - m);
                float e1 = __expf(p.y - m);
                s += e0 + e1;
                hp[j] = __floats2half2_rn(e0, e1);
            }
        }
#pragma unroll
        for (int o = 16; o > 0; o >>= 1)
            s += __shfl_xor_sync(0xFFFFFFFFu, s, o);
        const float inv = __frcp_rn(s);

#pragma unroll
        for (int i = 0; i < 8; i++) {
            __half2* hp = (__half2*)&u[i];
#pragma unroll
            for (int j = 0; j < 4; j++) {
                float2 p = __half22float2(hp[j]);
                acc[i][j * 2]     += p.x * inv;
                acc[i][j * 2 + 1] += p.y * inv;
            }
        }
    }

    // combine warps in smem
#pragma unroll
    for (int i = 0; i < 8; i++)
#pragma unroll
        for (int j = 0; j < 8; j++)
            atomicAdd(&sacc[(lid + 32 * i) * 8 + j], acc[i][j]);
    __syncthreads();

    float* o = g_wp + ((long long)b * 8 + qc) * 2048;
    for (int i = tid; i < 2048; i += 256) o[i] = sacc[i];
}

__global__ void wreduce_kernel() {
    const int i = blockIdx.x * 256 + threadIdx.x;     // 0..32767
    const int b = i >> 11, k = i & 2047;
    float s = 0.0f;
#pragma unroll
    for (int j = 0; j < 8; j++) s += g_wp[((long long)b * 8 + j) * 2048 + k];
    g_w[i] = s;
}

// ---------------------------------------------------------------------------
// Final contraction, parallel over k-chunks: partials then reduce.
// ---------------------------------------------------------------------------
__global__ void out_part_kernel() {
    const int b = blockIdx.x;
    const int kc = blockIdx.y;
    const int d = threadIdx.x;
    const float* w = g_w + b * 2048 + kc * 256;
    const float* v = g_v + ((long long)b * 2048 + kc * 256) * 256 + d;
    float acc = 0.0f;
#pragma unroll 8
    for (int k = 0; k < 256; k++)
        acc = fmaf(w[k], v[(long long)k * 256], acc);
    g_op[((long long)b * 8 + kc) * 256 + d] = acc;
}

__global__ void out_reduce_kernel(float* __restrict__ out) {
    const int b = blockIdx.x;
    const int d = threadIdx.x;
    float s = 0.0f;
#pragma unroll
    for (int j = 0; j < 8; j++) s += g_op[((long long)b * 8 + j) * 256 + d];
    out[b * 256 + d] = s;
}

// ---------------------------------------------------------------------------
extern "C" void kernel_launch(void* const* d_in, const int* in_sizes, int n_in,
                              void* d_out, int out_size) {
    (void)in_sizes; (void)n_in; (void)out_size;
    const float* x  = (const float*)d_in[0];
    const float* Wq = (const float*)d_in[1];
    const float* bq = (const float*)d_in[2];
    const float* Wk = (const float*)d_in[3];
    const float* bk = (const float*)d_in[4];
    const float* Wv = (const float*)d_in[5];
    const float* bv = (const float*)d_in[6];
    float* out = (float*)d_out;

    __half *pxs, *pwtq, *pwtk, *pwtv, *pqs, *pks, *pe;
    float *pv;
    cudaGetSymbolAddress((void**)&pxs, g_xs);
    cudaGetSymbolAddress((void**)&pwtq, g_wtq);
    cudaGetSymbolAddress((void**)&pwtk, g_wtk);
    cudaGetSymbolAddress((void**)&pwtv, g_wtv);
    cudaGetSymbolAddress((void**)&pqs, g_qs);
    cudaGetSymbolAddress((void**)&pks, g_ks);
    cudaGetSymbolAddress((void**)&pv, g_v);
    cudaGetSymbolAddress((void**)&pe, g_energy);

    static int attr_done = 0;
    if (!attr_done) {
        cudaFuncSetAttribute(hmma_gemm<0, 256>, cudaFuncAttributeMaxDynamicSharedMemorySize, SMEM_BYTES);
        cudaFuncSetAttribute(hmma_gemm<1, 768>, cudaFuncAttributeMaxDynamicSharedMemorySize, SMEM_BYTES);
        cudaFuncSetAttribute(hmma_gemm<2, 512>, cudaFuncAttributeMaxDynamicSharedMemorySize, SMEM_BYTES);
        attr_done = 1;
    }

    // 1) splits
    split_x_kernel<<<32768, 256>>>(x);
    split_w_kernel<<<256, 256>>>(Wq, pwtq);
    split_w_kernel<<<256, 256>>>(Wk, pwtk);
    split_w_kernel<<<256, 256>>>(Wv, pwtv);

    // 2) projections: M=32768, N=256 (2 tiles). q,k 2-term K=512; v 3-term K=768.
    dim3 gproj(2, 256, 1);
    hmma_gemm<2, 512><<<gproj, 128, SMEM_BYTES>>>(pxs, pwtq, bq, nullptr, pqs,
                                                  KSPLIT, KSPLIT, 0, 0, 1.0f);
    hmma_gemm<2, 512><<<gproj, 128, SMEM_BYTES>>>(pxs, pwtk, bk, nullptr, pks,
                                                  KSPLIT, KSPLIT, 0, 0, 1.0f);
    hmma_gemm<1, 768><<<gproj, 128, SMEM_BYTES>>>(pxs, pwtv, bv, pv, nullptr,
                                                  KSPLIT, KSPLIT, 0, 0, 1.0f);

    // 3) energy = q_hi k_hi^T / 16, batched, K=256
    dim3 gen(16, 16, 16);
    hmma_gemm<0, 256><<<gen, 128, SMEM_BYTES>>>(pqs, pks, nullptr, nullptr, pe,
                                                256, 256,
                                                (long long)2048 * 256,
                                                (long long)2048 * 256, 0.0625f);

    // 4) fused softmax colsum (single pass), reduce
    colsum_fused_kernel<<<dim3(16, 8), 256>>>();
    wreduce_kernel<<<128, 256>>>();

    // 5) final contraction
    out_part_kernel<<<dim3(16, 8), 256>>>();
    out_reduce_kernel<<<16, 256>>>(out);
}